// round 1
// baseline (speedup 1.0000x reference)
#include <cuda_runtime.h>

#define CC 32
#define DD 48
#define HH 64
#define WW 208
#define HW 13312            // HH*WW
#define NELEM (CC*DD*HH*WW) // 20447232
#define CEPS 1e-5f

// ---------- scratch (device globals: allocation-free) ----------
__device__ float g_kn[4 * 5 * HW];     // normalized guidance, [dir][j][h][w]
__device__ float g_xt[NELEM];          // x transposed to [d][h][w][c]
__device__ float g_accA[NELEM];        // dir1 then max(dir1,dir3) then final max
__device__ float g_accB[NELEM];        // dir2 then max(dir2,dir4)
__device__ float g_wre[27 * 32 * 32];  // weights [tap][ic][oc], pre-scaled by bn2
__device__ float g_bias2[32];
__device__ float g_s1v[32];
__device__ float g_b1v[32];

// ---------- packed f32x2 helpers (Blackwell FFMA2) ----------
__device__ __forceinline__ unsigned long long pk2(float lo, float hi) {
    unsigned long long r;
    asm("mov.b64 %0, {%1, %2};" : "=l"(r) : "f"(lo), "f"(hi));
    return r;
}
__device__ __forceinline__ unsigned long long ffma2(unsigned long long a,
                                                    unsigned long long b,
                                                    unsigned long long c) {
    unsigned long long d;
    asm("fma.rn.f32x2 %0, %1, %2, %3;" : "=l"(d) : "l"(a), "l"(b), "l"(c));
    return d;
}
__device__ __forceinline__ float2 upk2(unsigned long long v) {
    float lo, hi;
    asm("mov.b64 {%0, %1}, %2;" : "=f"(lo), "=f"(hi) : "l"(v));
    return make_float2(lo, hi);
}

// ---------- 1) guidance L1 normalization ----------
__global__ void k_norm(const float* __restrict__ g) {
    int i = blockIdx.x * blockDim.x + threadIdx.x;   // over 4*HW
    if (i >= 4 * HW) return;
    int dir = i / HW;
    int hw  = i % HW;
    float v[5];
    float s = 0.f;
#pragma unroll
    for (int j = 0; j < 5; j++) {
        v[j] = g[(5 * dir + j) * HW + hw];
        s += fabsf(v[j]);
    }
    float inv = 1.f / fmaxf(s, 1e-12f);
#pragma unroll
    for (int j = 0; j < 5; j++)
        g_kn[(dir * 5 + j) * HW + hw] = v[j] * inv;
}

// ---------- 2) transpose NCDHW -> [d][h][w][c] ----------
__global__ void k_transpose(const float* __restrict__ x) {
    __shared__ float t[32][209];
    int d = blockIdx.x / HH;
    int h = blockIdx.x % HH;
    for (int i = threadIdx.x; i < 32 * WW; i += blockDim.x) {
        int c = i / WW, w = i % WW;
        t[c][w] = x[((c * DD + d) * HH + h) * WW + w];
    }
    __syncthreads();
    float* dst = g_xt + (d * HH + h) * WW * 32;
    for (int i = threadIdx.x; i < WW * 32; i += blockDim.x) {
        dst[i] = t[i & 31][i >> 5];
    }
}

// ---------- 3) weight prep: fold BN2 into weights, BN1 into scale/shift ----------
__global__ void k_prep(const float* __restrict__ cw,
                       const float* __restrict__ g1, const float* __restrict__ b1,
                       const float* __restrict__ m1, const float* __restrict__ v1,
                       const float* __restrict__ g2, const float* __restrict__ b2,
                       const float* __restrict__ m2, const float* __restrict__ v2) {
    int i = blockIdx.x * blockDim.x + threadIdx.x;
    if (i < 27 * 1024) {
        int tap = i >> 10;
        int r   = i & 1023;
        int ic  = r >> 5;
        int oc  = r & 31;
        float s2 = g2[oc] * rsqrtf(v2[oc] + CEPS);
        g_wre[tap * 1024 + ic * 32 + oc] = cw[(oc * 32 + ic) * 27 + tap] * s2;
    }
    if (i < 32) {
        float s2 = g2[i] * rsqrtf(v2[i] + CEPS);
        g_bias2[i] = b2[i] - m2[i] * s2;
        float s1 = g1[i] * rsqrtf(v1[i] + CEPS);
        g_s1v[i] = s1;
        g_b1v[i] = b1[i] - m1[i] * s1;
    }
}

// ---------- 4) W-direction scans (dir1 fwd -> accA, dir2 bwd -> accB) ----------
// thread = (c=lane, h); all 48 D values live in registers.
__global__ void __launch_bounds__(128) k_wscan() {
    int c   = threadIdx.x;
    int h   = blockIdx.x * 4 + threadIdx.y;
    int dir = blockIdx.y;
    const float* kb = g_kn + dir * 5 * HW + h * WW;
    float* ob = dir ? g_accB : g_accA;
    int p0 = dir ? (WW - 1) : 0;
    int ps = dir ? -1 : 1;
    int base = h * WW;

    float A[48];
    float mx = -3.402823e38f;
#pragma unroll
    for (int d = 0; d < 48; d++) {
        A[d] = g_xt[(d * HW + base + p0) * 32 + c];
        mx = fmaxf(mx, A[d]);
    }
    int p = p0;
    for (int s = 0; s < WW; s++, p += ps) {
        float w0 = kb[p];
        float w1 = kb[HW + p];
        float w2 = kb[2 * HW + p];
        float w3 = kb[3 * HW + p];
        float w4 = kb[4 * HW + p];
        float xv[48];
#pragma unroll
        for (int d = 0; d < 48; d++)
            xv[d] = g_xt[(d * HW + base + p) * 32 + c];
        float nmx = -3.402823e38f;
        float prevOld = A[0];
#pragma unroll
        for (int d = 0; d < 48; d++) {
            float old = A[d];
            float up  = (d == 0) ? old : prevOld;
            float dn  = (d == 47) ? old : A[d + 1];
            float nv  = w0 * xv[d] + w1 * old + w2 * up + w3 * dn + w4 * mx;
            ob[(d * HW + base + p) * 32 + c] = nv;
            A[d] = nv;
            prevOld = old;
            nmx = fmaxf(nmx, nv);
        }
        mx = nmx;
    }
}

// ---------- 5) H-direction scans (dir3 fwd max->accA, dir4 bwd max->accB) ----------
__global__ void __launch_bounds__(128) k_hscan() {
    int c   = threadIdx.x;
    int w   = blockIdx.x * 4 + threadIdx.y;
    int dir = blockIdx.y;
    const float* kb = g_kn + (2 + dir) * 5 * HW + w;
    float* ob = dir ? g_accB : g_accA;
    int h0 = dir ? (HH - 1) : 0;
    int hs = dir ? -1 : 1;

    float A[48];
    float mx = -3.402823e38f;
#pragma unroll
    for (int d = 0; d < 48; d++) {
        A[d] = g_xt[(d * HW + h0 * WW + w) * 32 + c];
        mx = fmaxf(mx, A[d]);
    }
    int h = h0;
    for (int s = 0; s < HH; s++, h += hs) {
        float w0 = kb[h * WW];
        float w1 = kb[HW + h * WW];
        float w2 = kb[2 * HW + h * WW];
        float w3 = kb[3 * HW + h * WW];
        float w4 = kb[4 * HW + h * WW];
        float xv[48];
#pragma unroll
        for (int d = 0; d < 48; d++)
            xv[d] = g_xt[(d * HW + h * WW + w) * 32 + c];
        float nmx = -3.402823e38f;
        float prevOld = A[0];
#pragma unroll
        for (int d = 0; d < 48; d++) {
            float old = A[d];
            float up  = (d == 0) ? old : prevOld;
            float dn  = (d == 47) ? old : A[d + 1];
            float nv  = w0 * xv[d] + w1 * old + w2 * up + w3 * dn + w4 * mx;
            int idx = (d * HW + h * WW + w) * 32 + c;
            ob[idx] = fmaxf(ob[idx], nv);
            A[d] = nv;
            prevOld = old;
            nmx = fmaxf(nmx, nv);
        }
        mx = nmx;
    }
}

// ---------- 6) combine accA = max(accA, accB) ----------
__global__ void k_combine() {
    int i = blockIdx.x * blockDim.x + threadIdx.x;
    if (i >= NELEM / 4) return;
    float4* a = (float4*)g_accA;
    const float4* b = (const float4*)g_accB;
    float4 x = a[i];
    float4 y = b[i];
    x.x = fmaxf(x.x, y.x);
    x.y = fmaxf(x.y, y.y);
    x.z = fmaxf(x.z, y.z);
    x.w = fmaxf(x.w, y.w);
    a[i] = x;
}

// ---------- 7) conv3d 3x3x3 + BN1/ReLU on input + BN2 + residual + ReLU ----------
// block = one (d,h); 128 threads = 4 oc-quads x 32 w-group lanes (26 active).
// per thread: 8 w x 8 oc register tile, packed f32x2 FMAs.
__global__ void __launch_bounds__(128) k_conv(const float* __restrict__ xres,
                                              float* __restrict__ out) {
    __shared__ float a_sm[32][212];     // [ic][w+1], zero-padded borders
    __shared__ float w_sm[3 * 1024];    // [kw][ic][oc] for current (kd,kh)
    __shared__ float s1s[32], b1s[32], bias2s[32];

    int tid = threadIdx.x;
    int h = blockIdx.x;
    int d = blockIdx.y;
    int ocq = tid >> 5;        // 0..3 -> oc base 8*ocq
    int wg  = tid & 31;        // 0..25 active -> w base 8*wg

    if (tid < 32) {
        s1s[tid] = g_s1v[tid];
        b1s[tid] = g_b1v[tid];
        bias2s[tid] = g_bias2[tid];
    }
    for (int i = tid; i < 32 * 212; i += 128)
        ((float*)a_sm)[i] = 0.f;
    __syncthreads();

    unsigned long long acc2[8][4];
#pragma unroll
    for (int o = 0; o < 8; o++)
#pragma unroll
        for (int t = 0; t < 4; t++) acc2[o][t] = 0ull;

#pragma unroll
    for (int kd = 0; kd < 3; kd++) {
        int din = d + kd - 1;
        if ((unsigned)din >= DD) continue;
#pragma unroll
        for (int kh = 0; kh < 3; kh++) {
            int hin = h + kh - 1;
            if ((unsigned)hin >= HH) continue;
            __syncthreads();
            // load input row [208][32] -> a_sm[ic][w+1] with BN1+ReLU
            const float4* src = (const float4*)(g_accA + ((din * HH + hin) * WW) * 32);
            for (int i = tid; i < (WW * 32) / 4; i += 128) {
                float4 v = src[i];
                int c = (i * 4) & 31;
                int w = (i * 4) >> 5;
                a_sm[c + 0][w + 1] = fmaxf(v.x * s1s[c + 0] + b1s[c + 0], 0.f);
                a_sm[c + 1][w + 1] = fmaxf(v.y * s1s[c + 1] + b1s[c + 1], 0.f);
                a_sm[c + 2][w + 1] = fmaxf(v.z * s1s[c + 2] + b1s[c + 2], 0.f);
                a_sm[c + 3][w + 1] = fmaxf(v.w * s1s[c + 3] + b1s[c + 3], 0.f);
            }
            // load weight slab for 3 kw taps
            const float4* wsrc = (const float4*)(g_wre + (kd * 9 + kh * 3) * 1024);
            for (int i = tid; i < 3072 / 4; i += 128)
                ((float4*)w_sm)[i] = wsrc[i];
            __syncthreads();

            if (wg < 26) {
#pragma unroll 4
                for (int ic = 0; ic < 32; ic++) {
                    float4 av0 = *(const float4*)&a_sm[ic][8 * wg];
                    float4 av1 = *(const float4*)&a_sm[ic][8 * wg + 4];
                    float4 av2 = *(const float4*)&a_sm[ic][8 * wg + 8];
                    float a12[12] = {av0.x, av0.y, av0.z, av0.w,
                                     av1.x, av1.y, av1.z, av1.w,
                                     av2.x, av2.y, av2.z, av2.w};
#pragma unroll
                    for (int kw = 0; kw < 3; kw++) {
                        const float* wp = &w_sm[kw * 1024 + ic * 32 + 8 * ocq];
                        float4 wv0 = *(const float4*)wp;
                        float4 wv1 = *(const float4*)(wp + 4);
                        float wv[8] = {wv0.x, wv0.y, wv0.z, wv0.w,
                                       wv1.x, wv1.y, wv1.z, wv1.w};
                        unsigned long long apr[4];
#pragma unroll
                        for (int t = 0; t < 4; t++)
                            apr[t] = pk2(a12[2 * t + kw], a12[2 * t + 1 + kw]);
#pragma unroll
                        for (int o = 0; o < 8; o++) {
                            unsigned long long wpr = pk2(wv[o], wv[o]);
#pragma unroll
                            for (int t = 0; t < 4; t++)
                                acc2[o][t] = ffma2(wpr, apr[t], acc2[o][t]);
                        }
                    }
                }
            }
        }
    }

    // epilogue: +bias2 (BN2 folded), +residual, ReLU, write NCDHW
    if (wg < 26) {
#pragma unroll
        for (int o = 0; o < 8; o++) {
            int oc = 8 * ocq + o;
            int base = ((oc * DD + d) * HH + h) * WW + 8 * wg;
            float bi = bias2s[oc];
#pragma unroll
            for (int t = 0; t < 4; t++) {
                float2 f = upk2(acc2[o][t]);
                float2 r = *(const float2*)&xres[base + 2 * t];
                float o0 = fmaxf(f.x + bi + r.x, 0.f);
                float o1 = fmaxf(f.y + bi + r.y, 0.f);
                *(float2*)&out[base + 2 * t] = make_float2(o0, o1);
            }
        }
    }
}

// ---------- launcher ----------
extern "C" void kernel_launch(void* const* d_in, const int* in_sizes, int n_in,
                              void* d_out, int out_size) {
    const float* x  = (const float*)d_in[0];
    const float* g  = (const float*)d_in[1];
    const float* cw = (const float*)d_in[2];
    const float* g1 = (const float*)d_in[3];
    const float* b1 = (const float*)d_in[4];
    const float* m1 = (const float*)d_in[5];
    const float* v1 = (const float*)d_in[6];
    const float* g2 = (const float*)d_in[7];
    const float* b2 = (const float*)d_in[8];
    const float* m2 = (const float*)d_in[9];
    const float* v2 = (const float*)d_in[10];
    float* out = (float*)d_out;

    k_norm<<<(4 * HW + 255) / 256, 256>>>(g);
    k_prep<<<(27 * 1024 + 255) / 256, 256>>>(cw, g1, b1, m1, v1, g2, b2, m2, v2);
    k_transpose<<<DD * HH, 256>>>(x);
    k_wscan<<<dim3(16, 2), dim3(32, 4)>>>();
    k_hscan<<<dim3(52, 2), dim3(32, 4)>>>();
    k_combine<<<(NELEM / 4 + 255) / 256, 256>>>();
    k_conv<<<dim3(HH, DD), 128>>>(x, out);
}

// round 2
// speedup vs baseline: 1.2733x; 1.2733x over previous
#include <cuda_runtime.h>

#define CC 32
#define DD 48
#define HH 64
#define WW 208
#define HW 13312            // HH*WW
#define NELEM (CC*DD*HH*WW) // 20447232
#define CEPS 1e-5f
#define NEGINF -3.402823e38f

typedef unsigned long long ull;

// ---------- scratch (device globals: allocation-free) ----------
__device__ float g_kn[4 * 5 * HW];       // normalized guidance, [dir][j][h][w]
__device__ float g_xt[NELEM];            // x transposed [d][h][w][c]; later reused as act [d][h][c][w]
__device__ float g_accA[NELEM];          // dir1 then max(dir1,dir3)
__device__ float g_accB[NELEM];          // dir2 then max(dir2,dir4)
__device__ float g_wdup[27 * 32 * 32 * 2]; // weights [tap][ic][oc] duplicated pairs, bn2-scaled
__device__ float g_bias2[32];
__device__ float g_s1v[32];
__device__ float g_b1v[32];

// ---------- packed f32x2 helpers (Blackwell FFMA2) ----------
__device__ __forceinline__ ull pk2(float lo, float hi) {
    ull r;
    asm("mov.b64 %0, {%1, %2};" : "=l"(r) : "f"(lo), "f"(hi));
    return r;
}
__device__ __forceinline__ ull ffma2(ull a, ull b, ull c) {
    ull d;
    asm("fma.rn.f32x2 %0, %1, %2, %3;" : "=l"(d) : "l"(a), "l"(b), "l"(c));
    return d;
}
__device__ __forceinline__ float2 upk2(ull v) {
    float lo, hi;
    asm("mov.b64 {%0, %1}, %2;" : "=f"(lo), "=f"(hi) : "l"(v));
    return make_float2(lo, hi);
}

// ---------- 1) guidance L1 normalization ----------
__global__ void k_norm(const float* __restrict__ g) {
    int i = blockIdx.x * blockDim.x + threadIdx.x;
    if (i >= 4 * HW) return;
    int dir = i / HW;
    int hw  = i % HW;
    float v[5];
    float s = 0.f;
#pragma unroll
    for (int j = 0; j < 5; j++) {
        v[j] = g[(5 * dir + j) * HW + hw];
        s += fabsf(v[j]);
    }
    float inv = 1.f / fmaxf(s, 1e-12f);
#pragma unroll
    for (int j = 0; j < 5; j++)
        g_kn[(dir * 5 + j) * HW + hw] = v[j] * inv;
}

// ---------- 2) transpose NCDHW -> [d][h][w][c] ----------
__global__ void k_transpose(const float* __restrict__ x) {
    __shared__ float t[32][209];
    int d = blockIdx.x / HH;
    int h = blockIdx.x % HH;
    for (int i = threadIdx.x; i < 32 * WW; i += blockDim.x) {
        int c = i / WW, w = i % WW;
        t[c][w] = x[((c * DD + d) * HH + h) * WW + w];
    }
    __syncthreads();
    float* dst = g_xt + (d * HH + h) * WW * 32;
    for (int i = threadIdx.x; i < WW * 32; i += blockDim.x) {
        dst[i] = t[i & 31][i >> 5];
    }
}

// ---------- 3) weight prep: fold BN2 into dup-pair weights, BN1 scale/shift ----------
__global__ void k_prep(const float* __restrict__ cw,
                       const float* __restrict__ g1, const float* __restrict__ b1,
                       const float* __restrict__ m1, const float* __restrict__ v1,
                       const float* __restrict__ g2, const float* __restrict__ b2,
                       const float* __restrict__ m2, const float* __restrict__ v2) {
    int i = blockIdx.x * blockDim.x + threadIdx.x;
    if (i < 27 * 1024) {
        int tap = i >> 10;
        int r   = i & 1023;
        int ic  = r >> 5;
        int oc  = r & 31;
        float s2 = g2[oc] * rsqrtf(v2[oc] + CEPS);
        float wv = cw[(oc * 32 + ic) * 27 + tap] * s2;
        g_wdup[i * 2 + 0] = wv;
        g_wdup[i * 2 + 1] = wv;
    }
    if (i < 32) {
        float s2 = g2[i] * rsqrtf(v2[i] + CEPS);
        g_bias2[i] = b2[i] - m2[i] * s2;
        float s1 = g1[i] * rsqrtf(v1[i] + CEPS);
        g_s1v[i] = s1;
        g_b1v[i] = b1[i] - m1[i] * s1;
    }
}

// ---------- 4) W-direction scans: warp = 4 D-slices x 8 channels ----------
// grid (HH, 2 dirs, 4 c-groups), block 32.
__global__ void __launch_bounds__(32) k_wscan() {
    int lane = threadIdx.x;
    int ds = lane >> 3;                 // D slice 0..3 (12 d's each)
    int c  = blockIdx.z * 8 + (lane & 7);
    int h  = blockIdx.x;
    int dir = blockIdx.y;
    const float* kb = g_kn + dir * 5 * HW + h * WW;
    float* ob = dir ? g_accB : g_accA;
    int p0 = dir ? (WW - 1) : 0;
    int ps = dir ? -1 : 1;
    int base = h * WW;
    int d0 = ds * 12;

    float A[12];
    float lmx = NEGINF;
#pragma unroll
    for (int j = 0; j < 12; j++) {
        A[j] = g_xt[((d0 + j) * HW + base + p0) * 32 + c];
        lmx = fmaxf(lmx, A[j]);
    }
    float gmx = fmaxf(lmx, __shfl_xor_sync(0xffffffffu, lmx, 8));
    gmx = fmaxf(gmx, __shfl_xor_sync(0xffffffffu, gmx, 16));

    int p = p0;
    for (int s = 0; s < WW; s++, p += ps) {
        float w0 = kb[p];
        float w1 = kb[HW + p];
        float w2 = kb[2 * HW + p];
        float w3 = kb[3 * HW + p];
        float w4 = kb[4 * HW + p];
        float fromUp = __shfl_up_sync(0xffffffffu, A[11], 8);
        float fromDn = __shfl_down_sync(0xffffffffu, A[0], 8);
        float xv[12];
#pragma unroll
        for (int j = 0; j < 12; j++)
            xv[j] = g_xt[((d0 + j) * HW + base + p) * 32 + c];
        float up0   = (ds == 0) ? A[0]  : fromUp;
        float dnTop = (ds == 3) ? A[11] : fromDn;
        float nmx = NEGINF;
        float prevOld = A[0];
#pragma unroll
        for (int j = 0; j < 12; j++) {
            float old = A[j];
            float up = (j == 0) ? up0 : prevOld;
            float dn = (j == 11) ? dnTop : A[j + 1];
            float nv = w0 * xv[j] + w1 * old + w2 * up + w3 * dn + w4 * gmx;
            ob[((d0 + j) * HW + base + p) * 32 + c] = nv;
            A[j] = nv;
            prevOld = old;
            nmx = fmaxf(nmx, nv);
        }
        float t = fmaxf(nmx, __shfl_xor_sync(0xffffffffu, nmx, 8));
        gmx = fmaxf(t, __shfl_xor_sync(0xffffffffu, t, 16));
    }
}

// ---------- 5) H-direction scans, RMW max into accA/accB ----------
// grid (WW, 2 dirs, 4 c-groups), block 32.
__global__ void __launch_bounds__(32) k_hscan() {
    int lane = threadIdx.x;
    int ds = lane >> 3;
    int c  = blockIdx.z * 8 + (lane & 7);
    int w  = blockIdx.x;
    int dir = blockIdx.y;
    const float* kb = g_kn + (2 + dir) * 5 * HW + w;
    float* ob = dir ? g_accB : g_accA;
    int h0 = dir ? (HH - 1) : 0;
    int hs = dir ? -1 : 1;
    int d0 = ds * 12;

    float A[12];
    float lmx = NEGINF;
#pragma unroll
    for (int j = 0; j < 12; j++) {
        A[j] = g_xt[((d0 + j) * HW + h0 * WW + w) * 32 + c];
        lmx = fmaxf(lmx, A[j]);
    }
    float gmx = fmaxf(lmx, __shfl_xor_sync(0xffffffffu, lmx, 8));
    gmx = fmaxf(gmx, __shfl_xor_sync(0xffffffffu, gmx, 16));

    int h = h0;
    for (int s = 0; s < HH; s++, h += hs) {
        float w0 = kb[h * WW];
        float w1 = kb[HW + h * WW];
        float w2 = kb[2 * HW + h * WW];
        float w3 = kb[3 * HW + h * WW];
        float w4 = kb[4 * HW + h * WW];
        float fromUp = __shfl_up_sync(0xffffffffu, A[11], 8);
        float fromDn = __shfl_down_sync(0xffffffffu, A[0], 8);
        float xv[12];
#pragma unroll
        for (int j = 0; j < 12; j++)
            xv[j] = g_xt[((d0 + j) * HW + h * WW + w) * 32 + c];
        float up0   = (ds == 0) ? A[0]  : fromUp;
        float dnTop = (ds == 3) ? A[11] : fromDn;
        float nmx = NEGINF;
        float prevOld = A[0];
#pragma unroll
        for (int j = 0; j < 12; j++) {
            float old = A[j];
            float up = (j == 0) ? up0 : prevOld;
            float dn = (j == 11) ? dnTop : A[j + 1];
            float nv = w0 * xv[j] + w1 * old + w2 * up + w3 * dn + w4 * gmx;
            int idx = ((d0 + j) * HW + h * WW + w) * 32 + c;
            ob[idx] = fmaxf(ob[idx], nv);
            A[j] = nv;
            prevOld = old;
            nmx = fmaxf(nmx, nv);
        }
        float t = fmaxf(nmx, __shfl_xor_sync(0xffffffffu, nmx, 8));
        gmx = fmaxf(t, __shfl_xor_sync(0xffffffffu, t, 16));
    }
}

// ---------- 6) combine: relu(bn1(max(A,B))) + transpose [w][c] -> [c][w] into g_xt ----------
// block = one (d,h) row.
__global__ void __launch_bounds__(256) k_combine() {
    __shared__ float t_sm[32][212];
    __shared__ float s1s[32], b1s[32];
    int tid = threadIdx.x;
    int d = blockIdx.x / HH;
    int h = blockIdx.x % HH;
    if (tid < 32) { s1s[tid] = g_s1v[tid]; b1s[tid] = g_b1v[tid]; }
    __syncthreads();
    long long rb = (long long)(d * HH + h) * (WW * 32);
    const float4* pa = (const float4*)(g_accA + rb);
    const float4* pb = (const float4*)(g_accB + rb);
    for (int i = tid; i < (WW * 32) / 4; i += 256) {
        float4 a = pa[i];
        float4 b = pb[i];
        int c = (i * 4) & 31;
        int w = (i * 4) >> 5;
        t_sm[c + 0][w] = fmaxf(fmaxf(a.x, b.x) * s1s[c + 0] + b1s[c + 0], 0.f);
        t_sm[c + 1][w] = fmaxf(fmaxf(a.y, b.y) * s1s[c + 1] + b1s[c + 1], 0.f);
        t_sm[c + 2][w] = fmaxf(fmaxf(a.z, b.z) * s1s[c + 2] + b1s[c + 2], 0.f);
        t_sm[c + 3][w] = fmaxf(fmaxf(a.w, b.w) * s1s[c + 3] + b1s[c + 3], 0.f);
    }
    __syncthreads();
    // write [c][w] rows: g_xt reused as activation
    float* dst = g_xt + rb;
    for (int i = tid; i < 32 * 52; i += 256) {
        int c = i / 52, b = i % 52;
        float4 v = *(const float4*)&t_sm[c][4 * b];
        *(float4*)&dst[c * WW + 4 * b] = v;
    }
}

// ---------- 7) conv3d 3x3x3 (input pre-activated) + BN2 + residual + ReLU ----------
// block = one (d,h); 128 threads = 4 oc-quads x 32 wg lanes (26 active).
// a_sm rows XOR-swizzled at 16B-block granularity: phys_blk = b ^ (b>>1).
#define ASTR 264
__global__ void __launch_bounds__(128) k_conv(const float* __restrict__ xres,
                                              float* __restrict__ out) {
    __shared__ float a_sm[32 * ASTR];
    __shared__ float w_sm[3 * 1024 * 2];
    __shared__ float bias2s[32];

    int tid = threadIdx.x;
    int h = blockIdx.x;
    int d = blockIdx.y;
    int ocq = tid >> 5;
    int wg  = tid & 31;

    if (tid < 32) bias2s[tid] = g_bias2[tid];
    for (int i = tid; i < 32 * ASTR; i += 128) a_sm[i] = 0.f;

    // precomputed swizzled block offsets for this thread's 3 blocks
    int B0 = 2 * wg;
    int q0 = (B0 ^ (B0 >> 1)) * 4;
    int B1 = 2 * wg + 1;
    int q1 = (B1 ^ (B1 >> 1)) * 4;
    int B2 = 2 * wg + 2;
    int q2 = (B2 ^ (B2 >> 1)) * 4;

    ull acc[8][4];
#pragma unroll
    for (int o = 0; o < 8; o++)
#pragma unroll
        for (int t = 0; t < 4; t++) acc[o][t] = 0ull;

#pragma unroll
    for (int kd = 0; kd < 3; kd++) {
        int din = d + kd - 1;
        if ((unsigned)din >= DD) continue;
#pragma unroll
        for (int kh = 0; kh < 3; kh++) {
            int hin = h + kh - 1;
            if ((unsigned)hin >= HH) continue;
            __syncthreads();
            // load activation [c][w] rows into swizzled a_sm (logical col = w+1)
            const float* src = g_xt + (long long)((din * HH + hin)) * (WW * 32);
            for (int i = tid; i < 32 * 52; i += 128) {
                int ic = i / 52, b = i % 52;
                float4 v = *(const float4*)&src[ic * WW + 4 * b];
                float* ar = a_sm + ic * ASTR;
                int L0 = 4 * b + 1;
#pragma unroll
                for (int q = 0; q < 4; q++) {
                    int L = L0 + q;
                    int blk = L >> 2;
                    int pos = L & 3;
                    float val = (q == 0) ? v.x : (q == 1) ? v.y : (q == 2) ? v.z : v.w;
                    ar[(blk ^ (blk >> 1)) * 4 + pos] = val;
                }
            }
            // load dup weights for 3 kw taps: 6144 floats
            const float4* wsrc = (const float4*)(g_wdup + (kd * 9 + kh * 3) * 2048);
            for (int i = tid; i < 1536; i += 128)
                ((float4*)w_sm)[i] = wsrc[i];
            __syncthreads();

            if (wg < 26) {
#pragma unroll 4
                for (int ic = 0; ic < 32; ic++) {
                    const float* ar = a_sm + ic * ASTR;
                    float4 av0 = *(const float4*)(ar + q0);
                    float4 av1 = *(const float4*)(ar + q1);
                    float4 av2 = *(const float4*)(ar + q2);
                    ull E0 = pk2(av0.x, av0.y), E1 = pk2(av0.z, av0.w);
                    ull E2 = pk2(av1.x, av1.y), E3 = pk2(av1.z, av1.w);
                    ull E4 = pk2(av2.x, av2.y);
                    ull O0 = pk2(av0.y, av0.z), O1 = pk2(av0.w, av1.x);
                    ull O2 = pk2(av1.y, av1.z), O3 = pk2(av1.w, av2.x);
                    const ull* wrow = (const ull*)(w_sm) + ic * 32 + 8 * ocq;
#pragma unroll
                    for (int kw = 0; kw < 3; kw++) {
                        ull Ap0 = (kw == 0) ? E0 : (kw == 1) ? O0 : E1;
                        ull Ap1 = (kw == 0) ? E1 : (kw == 1) ? O1 : E2;
                        ull Ap2 = (kw == 0) ? E2 : (kw == 1) ? O2 : E3;
                        ull Ap3 = (kw == 0) ? E3 : (kw == 1) ? O3 : E4;
                        const ulonglong2* wp = (const ulonglong2*)(wrow + kw * 1024);
                        ulonglong2 wab = wp[0];
                        ulonglong2 wcd = wp[1];
                        ulonglong2 wef = wp[2];
                        ulonglong2 wgh = wp[3];
                        ull W[8] = {wab.x, wab.y, wcd.x, wcd.y,
                                    wef.x, wef.y, wgh.x, wgh.y};
#pragma unroll
                        for (int o = 0; o < 8; o++) {
                            acc[o][0] = ffma2(W[o], Ap0, acc[o][0]);
                            acc[o][1] = ffma2(W[o], Ap1, acc[o][1]);
                            acc[o][2] = ffma2(W[o], Ap2, acc[o][2]);
                            acc[o][3] = ffma2(W[o], Ap3, acc[o][3]);
                        }
                    }
                }
            }
        }
    }

    if (wg < 26) {
#pragma unroll
        for (int o = 0; o < 8; o++) {
            int oc = 8 * ocq + o;
            int base = ((oc * DD + d) * HH + h) * WW + 8 * wg;
            float bi = bias2s[oc];
#pragma unroll
            for (int t = 0; t < 4; t++) {
                float2 f = upk2(acc[o][t]);
                float2 r = *(const float2*)&xres[base + 2 * t];
                float o0 = fmaxf(f.x + bi + r.x, 0.f);
                float o1 = fmaxf(f.y + bi + r.y, 0.f);
                *(float2*)&out[base + 2 * t] = make_float2(o0, o1);
            }
        }
    }
}

// ---------- launcher ----------
extern "C" void kernel_launch(void* const* d_in, const int* in_sizes, int n_in,
                              void* d_out, int out_size) {
    const float* x  = (const float*)d_in[0];
    const float* g  = (const float*)d_in[1];
    const float* cw = (const float*)d_in[2];
    const float* g1 = (const float*)d_in[3];
    const float* b1 = (const float*)d_in[4];
    const float* m1 = (const float*)d_in[5];
    const float* v1 = (const float*)d_in[6];
    const float* g2 = (const float*)d_in[7];
    const float* b2 = (const float*)d_in[8];
    const float* m2 = (const float*)d_in[9];
    const float* v2 = (const float*)d_in[10];
    float* out = (float*)d_out;

    k_norm<<<(4 * HW + 255) / 256, 256>>>(g);
    k_prep<<<(27 * 1024 + 255) / 256, 256>>>(cw, g1, b1, m1, v1, g2, b2, m2, v2);
    k_transpose<<<DD * HH, 256>>>(x);
    k_wscan<<<dim3(HH, 2, 4), 32>>>();
    k_hscan<<<dim3(WW, 2, 4), 32>>>();
    k_combine<<<DD * HH, 256>>>();
    k_conv<<<dim3(HH, DD), 128>>>(x, out);
}